// round 1
// baseline (speedup 1.0000x reference)
#include <cuda_runtime.h>
#include <cuda_bf16.h>
#include <cstdint>

// ---------------- problem constants ----------------
#define NE 8           // experts
#define TKK 2          // top-k
#define HID 2048       // hidden
#define INTER 4096     // intermediate
#define MAXT 8192      // max tokens (4*2048)
#define MAXPAIRS (MAXT * TKK)

#define BM 128
#define BN 128
#define BKK 32

// ---------------- scratch (__device__ globals; no allocs allowed) ----------------
__device__ float g_act[(size_t)MAXPAIRS * INTER];       // gate -> act buffer (reused in-place)
__device__ float g_pair_out[(size_t)MAXPAIRS * HID];    // per (token,expert) down output
__device__ int   g_counts[NE];
__device__ int   g_offsets[NE + 1];
__device__ int   g_top_e[MAXT][TKK];
__device__ float g_top_w[MAXT][TKK];
__device__ int   g_pos[MAXT][TKK];
__device__ int   g_row_token[MAXPAIRS];
__device__ float g_row_weight[MAXPAIRS];
__device__ int   g_row_of[MAXT][TKK];

// ---------------- ptx helpers ----------------
__device__ __forceinline__ uint32_t smem_u32(const void* p) {
    return (uint32_t)__cvta_generic_to_shared(p);
}
__device__ __forceinline__ void ldm_x4(uint32_t* r, const void* p) {
    uint32_t a = smem_u32(p);
    asm volatile("ldmatrix.sync.aligned.m8n8.x4.shared.b16 {%0,%1,%2,%3}, [%4];"
                 : "=r"(r[0]), "=r"(r[1]), "=r"(r[2]), "=r"(r[3]) : "r"(a));
}
__device__ __forceinline__ void ldm_x4_t(uint32_t* r, const void* p) {
    uint32_t a = smem_u32(p);
    asm volatile("ldmatrix.sync.aligned.m8n8.x4.trans.shared.b16 {%0,%1,%2,%3}, [%4];"
                 : "=r"(r[0]), "=r"(r[1]), "=r"(r[2]), "=r"(r[3]) : "r"(a));
}
__device__ __forceinline__ void mma_bf16(float* c, const uint32_t* a, const uint32_t* b) {
    asm volatile("mma.sync.aligned.m16n8k16.row.col.f32.bf16.bf16.f32 "
                 "{%0,%1,%2,%3}, {%4,%5,%6,%7}, {%8,%9}, {%0,%1,%2,%3};"
                 : "+f"(c[0]), "+f"(c[1]), "+f"(c[2]), "+f"(c[3])
                 : "r"(a[0]), "r"(a[1]), "r"(a[2]), "r"(a[3]), "r"(b[0]), "r"(b[1]));
}

// ---------------- router: logits, softmax, top-2 ----------------
__global__ void router_kernel(const float* __restrict__ x, const float* __restrict__ wr, int T) {
    if (blockIdx.x == 0 && threadIdx.x < NE) g_counts[threadIdx.x] = 0;
    int gw = (blockIdx.x * blockDim.x + threadIdx.x) >> 5;
    int lane = threadIdx.x & 31;
    if (gw >= T) return;
    const float* xr = x + (size_t)gw * HID;
    float acc[NE];
#pragma unroll
    for (int e = 0; e < NE; e++) acc[e] = 0.f;
    for (int h = lane; h < HID; h += 32) {
        float xv = xr[h];
        const float* w = wr + (size_t)h * NE;
#pragma unroll
        for (int e = 0; e < NE; e++) acc[e] += xv * w[e];
    }
#pragma unroll
    for (int e = 0; e < NE; e++)
#pragma unroll
        for (int o = 16; o > 0; o >>= 1) acc[e] += __shfl_xor_sync(0xffffffffu, acc[e], o);
    if (lane == 0) {
        float m = acc[0];
#pragma unroll
        for (int e = 1; e < NE; e++) m = fmaxf(m, acc[e]);
        float p[NE], s = 0.f;
#pragma unroll
        for (int e = 0; e < NE; e++) { p[e] = expf(acc[e] - m); s += p[e]; }
        float inv = 1.f / s;
#pragma unroll
        for (int e = 0; e < NE; e++) p[e] *= inv;
        int i0 = 0;
#pragma unroll
        for (int e = 1; e < NE; e++) if (p[e] > p[i0]) i0 = e;
        int i1 = (i0 == 0) ? 1 : 0;
#pragma unroll
        for (int e = 0; e < NE; e++) if (e != i0 && p[e] > p[i1]) i1 = e;
        g_top_e[gw][0] = i0; g_top_w[gw][0] = p[i0];
        g_top_e[gw][1] = i1; g_top_w[gw][1] = p[i1];
    }
}

__global__ void assign_kernel(int pairs) {
    int i = blockIdx.x * blockDim.x + threadIdx.x;
    if (i >= pairs) return;
    int t = i >> 1, k = i & 1;
    int e = g_top_e[t][k];
    g_pos[t][k] = atomicAdd(&g_counts[e], 1);
}

__global__ void scan_kernel() {
    if (threadIdx.x == 0 && blockIdx.x == 0) {
        int s = 0;
        for (int e = 0; e < NE; e++) { g_offsets[e] = s; s += g_counts[e]; }
        g_offsets[NE] = s;
    }
}

__global__ void fill_kernel(int pairs) {
    int i = blockIdx.x * blockDim.x + threadIdx.x;
    if (i >= pairs) return;
    int t = i >> 1, k = i & 1;
    int e = g_top_e[t][k];
    int row = g_offsets[e] + g_pos[t][k];
    g_row_token[row] = t;
    g_row_weight[row] = g_top_w[t][k];
    g_row_of[t][k] = row;
}

// ---------------- grouped GEMM (bf16x3 split, fp32 accum) ----------------
// MODE 0: C = gather(x) @ Wg[e]           -> g_act (raw dot)
// MODE 1: C = gather(x) @ Wu[e]; epilogue: g_act = silu(0.5*g_act) * C
// MODE 2: C = g_act @ Wd[e];     epilogue: g_pair_out = 0.25 * w_row * C
template <int MODE, int KD, int ND>
__global__ void __launch_bounds__(256) moe_gemm(const float* __restrict__ X,
                                                const float* __restrict__ Wall) {
    constexpr int SA = BKK + 8;  // 40  (conflict-friendly padded stride)
    constexpr int SB = BN + 8;   // 136
    __shared__ __nv_bfloat16 sAh[BM][SA], sAl[BM][SA];
    __shared__ __nv_bfloat16 sBh[BKK][SB], sBl[BKK][SB];
    __shared__ const float* sPtr[BM];

    int e = blockIdx.z;
    int r0 = g_offsets[e];
    int ne = g_offsets[e + 1] - r0;
    int rowt = blockIdx.y * BM;
    if (rowt >= ne) return;
    int n0 = blockIdx.x * BN;
    const float* W = Wall + (size_t)e * KD * ND;

    int tid = threadIdx.x;
    if (tid < BM) {
        int gr = rowt + tid;
        const float* p = nullptr;
        if (gr < ne) {
            if (MODE < 2) p = X + (size_t)g_row_token[r0 + gr] * KD;
            else          p = g_act + (size_t)(r0 + gr) * KD;
        }
        sPtr[tid] = p;
    }

    int warp = tid >> 5, lane = tid & 31;
    int wm = warp >> 2;  // 0..1  (row group of 64)
    int wn = warp & 3;   // 0..3  (col group of 32)

    float acc[4][4][4];
#pragma unroll
    for (int a = 0; a < 4; a++)
#pragma unroll
        for (int b = 0; b < 4; b++)
#pragma unroll
            for (int c = 0; c < 4; c++) acc[a][b][c] = 0.f;

    for (int k0 = 0; k0 < KD; k0 += BKK) {
        __syncthreads();
        // A tile: 128x32 fp32 gathered -> hi/lo bf16
#pragma unroll
        for (int p = 0; p < 4; p++) {
            int r = (tid >> 3) + p * 32;
            int c = (tid & 7) * 4;
            const float* ap = sPtr[r];
            float4 v = make_float4(0.f, 0.f, 0.f, 0.f);
            if (ap) v = *reinterpret_cast<const float4*>(ap + k0 + c);
            float vv[4] = {v.x, v.y, v.z, v.w};
#pragma unroll
            for (int j = 0; j < 4; j++) {
                __nv_bfloat16 h = __float2bfloat16(vv[j]);
                sAh[r][c + j] = h;
                sAl[r][c + j] = __float2bfloat16(vv[j] - __bfloat162float(h));
            }
        }
        // B tile: 32x128 fp32 -> hi/lo bf16
#pragma unroll
        for (int p = 0; p < 4; p++) {
            int r = (tid >> 5) + p * 8;
            int c = (tid & 31) * 4;
            float4 v = *reinterpret_cast<const float4*>(W + (size_t)(k0 + r) * ND + n0 + c);
            float vv[4] = {v.x, v.y, v.z, v.w};
#pragma unroll
            for (int j = 0; j < 4; j++) {
                __nv_bfloat16 h = __float2bfloat16(vv[j]);
                sBh[r][c + j] = h;
                sBl[r][c + j] = __float2bfloat16(vv[j] - __bfloat162float(h));
            }
        }
        __syncthreads();
#pragma unroll
        for (int kk = 0; kk < BKK; kk += 16) {
            uint32_t ah[4][4], al[4][4];
#pragma unroll
            for (int mt = 0; mt < 4; mt++) {
                int ar = wm * 64 + mt * 16 + (lane & 15);
                int ac = kk + (lane >> 4) * 8;
                ldm_x4(ah[mt], &sAh[ar][ac]);
                ldm_x4(al[mt], &sAl[ar][ac]);
            }
            uint32_t bh[4][2], bl[4][2];
#pragma unroll
            for (int g = 0; g < 2; g++) {
                int br = kk + (lane & 15);
                int bc = wn * 32 + g * 16 + (lane >> 4) * 8;
                uint32_t t4[4];
                ldm_x4_t(t4, &sBh[br][bc]);
                bh[2 * g][0] = t4[0]; bh[2 * g][1] = t4[1];
                bh[2 * g + 1][0] = t4[2]; bh[2 * g + 1][1] = t4[3];
                ldm_x4_t(t4, &sBl[br][bc]);
                bl[2 * g][0] = t4[0]; bl[2 * g][1] = t4[1];
                bl[2 * g + 1][0] = t4[2]; bl[2 * g + 1][1] = t4[3];
            }
#pragma unroll
            for (int mt = 0; mt < 4; mt++)
#pragma unroll
                for (int nt = 0; nt < 4; nt++) {
                    mma_bf16(acc[mt][nt], ah[mt], bh[nt]);
                    mma_bf16(acc[mt][nt], al[mt], bh[nt]);
                    mma_bf16(acc[mt][nt], ah[mt], bl[nt]);
                }
        }
    }

    // epilogue
#pragma unroll
    for (int mt = 0; mt < 4; mt++)
#pragma unroll
        for (int nt = 0; nt < 4; nt++)
#pragma unroll
            for (int v = 0; v < 4; v++) {
                int rr = wm * 64 + mt * 16 + (lane >> 2) + ((v >= 2) ? 8 : 0);
                int cc = wn * 32 + nt * 8 + (lane & 3) * 2 + (v & 1);
                int gr = rowt + rr;
                if (gr < ne) {
                    size_t pr = (size_t)(r0 + gr);
                    float val = acc[mt][nt][v];
                    if (MODE == 0) {
                        g_act[pr * INTER + n0 + cc] = val;
                    } else if (MODE == 1) {
                        size_t idx = pr * INTER + n0 + cc;
                        float g = g_act[idx] * 0.5f;
                        float s = g / (1.f + expf(-g));
                        g_act[idx] = s * val;
                    } else {
                        float w = g_row_weight[pr];
                        g_pair_out[pr * HID + n0 + cc] = 0.25f * w * val;
                    }
                }
            }
}

// ---------------- combine: out[t] = pair_out[row(t,0)] + pair_out[row(t,1)] ----------------
__global__ void combine_kernel(float* __restrict__ out, int T) {
    int i = blockIdx.x * blockDim.x + threadIdx.x;  // float4 index
    int total = T * (HID / 4);
    if (i >= total) return;
    int t = i / (HID / 4);
    int c4 = i % (HID / 4);
    int ra = g_row_of[t][0], rb = g_row_of[t][1];
    float4 a = reinterpret_cast<const float4*>(g_pair_out + (size_t)ra * HID)[c4];
    float4 b = reinterpret_cast<const float4*>(g_pair_out + (size_t)rb * HID)[c4];
    float4 r;
    r.x = a.x + b.x; r.y = a.y + b.y; r.z = a.z + b.z; r.w = a.w + b.w;
    reinterpret_cast<float4*>(out)[i] = r;
}

// ---------------- launch ----------------
extern "C" void kernel_launch(void* const* d_in, const int* in_sizes, int n_in,
                              void* d_out, int out_size) {
    const float* x  = (const float*)d_in[0];
    const float* wr = (const float*)d_in[1];
    const float* wg = (const float*)d_in[2];
    const float* wu = (const float*)d_in[3];
    const float* wd = (const float*)d_in[4];
    float* out = (float*)d_out;

    int T = in_sizes[0] / HID;       // 8192
    int pairs = T * TKK;             // 16384

    // routing + compaction
    router_kernel<<<(T + 7) / 8, 256>>>(x, wr, T);
    assign_kernel<<<(pairs + 255) / 256, 256>>>(pairs);
    scan_kernel<<<1, 32>>>();
    fill_kernel<<<(pairs + 255) / 256, 256>>>(pairs);

    int rowTiles = (T + BM - 1) / BM;  // worst case: one expert gets every token
    // gate: gather(x) @ Wg -> g_act
    moe_gemm<0, HID, INTER><<<dim3(INTER / BN, rowTiles, NE), 256>>>(x, wg);
    // up: gather(x) @ Wu; epilogue fuses silu(0.5*g)*u -> g_act
    moe_gemm<1, HID, INTER><<<dim3(INTER / BN, rowTiles, NE), 256>>>(x, wu);
    // down: g_act @ Wd -> g_pair_out (weighted)
    moe_gemm<2, INTER, HID><<<dim3(HID / BN, rowTiles, NE), 256>>>(x, wd);

    // deterministic per-token combine (covers every output element; no memset needed)
    int tot4 = T * (HID / 4);
    combine_kernel<<<(tot4 + 255) / 256, 256>>>(out, T);
}

// round 8
// speedup vs baseline: 2.7864x; 2.7864x over previous
#include <cuda_runtime.h>
#include <cuda_bf16.h>
#include <cstdint>

// ---------------- problem constants ----------------
#define NE 8
#define TKK 2
#define HID 2048
#define INTER 4096
#define MAXT 8192
#define MAXPAIRS (MAXT * TKK)

// ---------------- scratch (__device__ globals) ----------------
__device__ __nv_bfloat16 g_acth[(size_t)MAXPAIRS * INTER];
__device__ __nv_bfloat16 g_actl[(size_t)MAXPAIRS * INTER];
__device__ float g_pair_out[(size_t)MAXPAIRS * HID];
__device__ __nv_bfloat16 g_xh[(size_t)MAXT * HID];
__device__ __nv_bfloat16 g_xl[(size_t)MAXT * HID];
__device__ __nv_bfloat16 g_wgh[(size_t)NE * HID * INTER];
__device__ __nv_bfloat16 g_wgl[(size_t)NE * HID * INTER];
__device__ __nv_bfloat16 g_wuh[(size_t)NE * HID * INTER];
__device__ __nv_bfloat16 g_wul[(size_t)NE * HID * INTER];
__device__ __nv_bfloat16 g_wdh[(size_t)NE * INTER * HID];
__device__ __nv_bfloat16 g_wdl[(size_t)NE * INTER * HID];
__device__ int   g_counts[NE];
__device__ int   g_offsets[NE + 1];
__device__ int   g_top_e[MAXT][TKK];
__device__ float g_top_w[MAXT][TKK];
__device__ int   g_pos[MAXT][TKK];
__device__ int   g_row_token[MAXPAIRS];
__device__ float g_row_weight[MAXPAIRS];
__device__ int   g_row_of[MAXT][TKK];

// ---------------- helpers ----------------
__device__ __forceinline__ uint32_t smem_u32(const void* p) {
    return (uint32_t)__cvta_generic_to_shared(p);
}
// SW128 swizzle on byte offsets within a 128B-row tile
#define SWZ(o) ((uint32_t)(o) ^ ((((uint32_t)(o)) >> 3) & 0x70u))

__device__ __forceinline__ void ldm4(uint32_t* r, uint32_t a) {
    asm volatile("ldmatrix.sync.aligned.m8n8.x4.shared.b16 {%0,%1,%2,%3}, [%4];"
                 : "=r"(r[0]), "=r"(r[1]), "=r"(r[2]), "=r"(r[3]) : "r"(a));
}
__device__ __forceinline__ void ldm4t(uint32_t* r, uint32_t a) {
    asm volatile("ldmatrix.sync.aligned.m8n8.x4.trans.shared.b16 {%0,%1,%2,%3}, [%4];"
                 : "=r"(r[0]), "=r"(r[1]), "=r"(r[2]), "=r"(r[3]) : "r"(a));
}
__device__ __forceinline__ void mma_bf16(float* c, const uint32_t* a, const uint32_t* b) {
    asm volatile("mma.sync.aligned.m16n8k16.row.col.f32.bf16.bf16.f32 "
                 "{%0,%1,%2,%3}, {%4,%5,%6,%7}, {%8,%9}, {%0,%1,%2,%3};"
                 : "+f"(c[0]), "+f"(c[1]), "+f"(c[2]), "+f"(c[3])
                 : "r"(a[0]), "r"(a[1]), "r"(a[2]), "r"(a[3]), "r"(b[0]), "r"(b[1]));
}
__device__ __forceinline__ void cp16(uint32_t dst, const void* src) {
    asm volatile("cp.async.ca.shared.global [%0], [%1], 16;" :: "r"(dst), "l"(src));
}
__device__ __forceinline__ void cp_commit() { asm volatile("cp.async.commit_group;" ::: "memory"); }
__device__ __forceinline__ void cp_wait0() { asm volatile("cp.async.wait_group 0;" ::: "memory"); }
__device__ __forceinline__ void cp_wait1() { asm volatile("cp.async.wait_group 1;" ::: "memory"); }
__device__ __forceinline__ void cp_wait2() { asm volatile("cp.async.wait_group 2;" ::: "memory"); }

// ---------------- router / compaction ----------------
__global__ void router_kernel(const float* __restrict__ x, const float* __restrict__ wr, int T) {
    if (blockIdx.x == 0 && threadIdx.x < NE) g_counts[threadIdx.x] = 0;
    int gw = (blockIdx.x * blockDim.x + threadIdx.x) >> 5;
    int lane = threadIdx.x & 31;
    if (gw >= T) return;
    const float* xr = x + (size_t)gw * HID;
    float acc[NE];
#pragma unroll
    for (int e = 0; e < NE; e++) acc[e] = 0.f;
    for (int h = lane; h < HID; h += 32) {
        float xv = xr[h];
        const float* w = wr + (size_t)h * NE;
#pragma unroll
        for (int e = 0; e < NE; e++) acc[e] += xv * w[e];
    }
#pragma unroll
    for (int e = 0; e < NE; e++)
#pragma unroll
        for (int o = 16; o > 0; o >>= 1) acc[e] += __shfl_xor_sync(0xffffffffu, acc[e], o);
    if (lane == 0) {
        float m = acc[0];
#pragma unroll
        for (int e = 1; e < NE; e++) m = fmaxf(m, acc[e]);
        float p[NE], s = 0.f;
#pragma unroll
        for (int e = 0; e < NE; e++) { p[e] = expf(acc[e] - m); s += p[e]; }
        float inv = 1.f / s;
#pragma unroll
        for (int e = 0; e < NE; e++) p[e] *= inv;
        int i0 = 0;
#pragma unroll
        for (int e = 1; e < NE; e++) if (p[e] > p[i0]) i0 = e;
        int i1 = (i0 == 0) ? 1 : 0;
#pragma unroll
        for (int e = 0; e < NE; e++) if (e != i0 && p[e] > p[i1]) i1 = e;
        g_top_e[gw][0] = i0; g_top_w[gw][0] = p[i0];
        g_top_e[gw][1] = i1; g_top_w[gw][1] = p[i1];
    }
}

__global__ void assign_kernel(int pairs) {
    int i = blockIdx.x * blockDim.x + threadIdx.x;
    if (i >= pairs) return;
    int t = i >> 1, k = i & 1;
    g_pos[t][k] = atomicAdd(&g_counts[g_top_e[t][k]], 1);
}

__global__ void scan_kernel() {
    if (threadIdx.x == 0 && blockIdx.x == 0) {
        int s = 0;
        for (int e = 0; e < NE; e++) { g_offsets[e] = s; s += g_counts[e]; }
        g_offsets[NE] = s;
    }
}

__global__ void fill_kernel(int pairs) {
    int i = blockIdx.x * blockDim.x + threadIdx.x;
    if (i >= pairs) return;
    int t = i >> 1, k = i & 1;
    int e = g_top_e[t][k];
    int row = g_offsets[e] + g_pos[t][k];
    g_row_token[row] = t;
    g_row_weight[row] = g_top_w[t][k];
    g_row_of[t][k] = row;
}

// ---------------- preconversion: fp32 -> bf16 hi/lo ----------------
// DST selects the destination globals IN DEVICE CODE (device-symbol addresses
// are only valid when taken on the device).
template <int DST>
__global__ void convert_kernel(const float* __restrict__ in, int n4) {
    __nv_bfloat16* oh;
    __nv_bfloat16* ol;
    if (DST == 0)      { oh = g_xh;  ol = g_xl;  }
    else if (DST == 1) { oh = g_wgh; ol = g_wgl; }
    else if (DST == 2) { oh = g_wuh; ol = g_wul; }
    else               { oh = g_wdh; ol = g_wdl; }
    int i = blockIdx.x * blockDim.x + threadIdx.x;
    if (i >= n4) return;
    float4 v = reinterpret_cast<const float4*>(in)[i];
    float vv[4] = {v.x, v.y, v.z, v.w};
    __nv_bfloat16 h[4], l[4];
#pragma unroll
    for (int j = 0; j < 4; j++) {
        h[j] = __float2bfloat16(vv[j]);
        l[j] = __float2bfloat16(vv[j] - __bfloat162float(h[j]));
    }
    reinterpret_cast<uint2*>(oh)[i] = *reinterpret_cast<uint2*>(h);
    reinterpret_cast<uint2*>(ol)[i] = *reinterpret_cast<uint2*>(l);
}

// ============================================================
// GEMM tiles: BM=128, BN=128, BK=64, 256 threads (8 warps 2x4),
// warp tile 64x32, bf16x3 split (hi*hi + lo*hi + hi*lo), fp32 acc.
// A tile smem: 128 rows x 128B (64 bf16), SW128 swizzled.
// B tile smem: two 64-col halves, each 64 rows x 128B, SW128.
// ============================================================

__device__ __forceinline__ void load_A(uint32_t dstH, uint32_t dstL, int tid,
                                       const __nv_bfloat16* __restrict__ Ah,
                                       const __nv_bfloat16* __restrict__ Al,
                                       const int* sRow, int k0) {
#pragma unroll
    for (int p = 0; p < 4; p++) {
        int idx = tid + p * 256;
        int row = idx >> 3, c = idx & 7;
        uint32_t sw = SWZ(row * 128 + c * 16);
        int off = sRow[row] + k0 + c * 8;
        cp16(dstH + sw, Ah + off);
        cp16(dstL + sw, Al + off);
    }
}
template <int ND>
__device__ __forceinline__ void load_B(uint32_t dstH, uint32_t dstL, int tid,
                                       const __nv_bfloat16* __restrict__ Bh,
                                       const __nv_bfloat16* __restrict__ Bl,
                                       int k0, int n0) {
#pragma unroll
    for (int p = 0; p < 4; p++) {
        int idx = tid + p * 256;
        int k = idx >> 4, cg = idx & 15;
        uint32_t sw = (uint32_t)(cg >> 3) * 8192 + SWZ(k * 128 + (cg & 7) * 16);
        size_t off = (size_t)(k0 + k) * ND + n0 + cg * 8;
        cp16(dstH + sw, Bh + off);
        cp16(dstL + sw, Bl + off);
    }
}

__device__ __forceinline__ void fragA(uint32_t base, int wm, int lane, int kk,
                                      uint32_t (*ah)[4]) {
#pragma unroll
    for (int mt = 0; mt < 4; mt++) {
        int ar = wm * 64 + mt * 16 + (lane & 15);
        int ac = kk + (lane >> 4) * 8;
        ldm4(ah[mt], base + SWZ(ar * 128 + ac * 2));
    }
}
__device__ __forceinline__ void fragB(uint32_t base, int wn, int lane, int kk,
                                      uint32_t (*bf)[2]) {
#pragma unroll
    for (int g = 0; g < 2; g++) {
        int br = kk + (lane & 15);
        int bc = wn * 32 + g * 16 + (lane >> 4) * 8;
        uint32_t addr = base + (uint32_t)(bc >> 6) * 8192 + SWZ(br * 128 + (bc & 63) * 2);
        uint32_t t4[4];
        ldm4t(t4, addr);
        bf[2 * g][0] = t4[0]; bf[2 * g][1] = t4[1];
        bf[2 * g + 1][0] = t4[2]; bf[2 * g + 1][1] = t4[3];
    }
}

// ---------------- fused gate+up GEMM ----------------
// stage layout: Ah 0, Al 16K, Bgh 32K, Bgl 48K, Buh 64K, Bul 80K (96KB/stage, 2 stages)
#define GU_STAGE 98304
#define GU_SMEM (2 * GU_STAGE)

__global__ void __launch_bounds__(256, 1)
moe_gateup() {
    constexpr int NC = HID / 64;
    extern __shared__ char dsm[];
    __shared__ int sRow[128];
    uint32_t sb = smem_u32(dsm);

    int e = blockIdx.z;
    int r0 = g_offsets[e];
    int ne = g_offsets[e + 1] - r0;
    int rowt = blockIdx.y * 128;
    if (rowt >= ne) return;
    int n0 = blockIdx.x * 128;
    int tid = threadIdx.x;

    const __nv_bfloat16* Bgh = g_wgh + (size_t)e * HID * INTER;
    const __nv_bfloat16* Bgl = g_wgl + (size_t)e * HID * INTER;
    const __nv_bfloat16* Buh = g_wuh + (size_t)e * HID * INTER;
    const __nv_bfloat16* Bul = g_wul + (size_t)e * HID * INTER;

    if (tid < 128) {
        int gr = min(rowt + tid, ne - 1);
        sRow[tid] = g_row_token[r0 + gr] * HID;
    }
    __syncthreads();

    auto load_stage = [&](int buf, int kc) {
        uint32_t bb = sb + buf * GU_STAGE;
        int k0 = kc * 64;
        load_A(bb, bb + 16384, tid, g_xh, g_xl, sRow, k0);
        load_B<INTER>(bb + 32768, bb + 49152, tid, Bgh, Bgl, k0, n0);
        load_B<INTER>(bb + 65536, bb + 81920, tid, Buh, Bul, k0, n0);
        cp_commit();
    };

    load_stage(0, 0);
    load_stage(1, 1);

    int warp = tid >> 5, lane = tid & 31;
    int wm = warp >> 2, wn = warp & 3;

    float accg[4][4][4], accu[4][4][4];
#pragma unroll
    for (int a = 0; a < 4; a++)
#pragma unroll
        for (int b = 0; b < 4; b++)
#pragma unroll
            for (int c = 0; c < 4; c++) { accg[a][b][c] = 0.f; accu[a][b][c] = 0.f; }

    for (int kc = 0; kc < NC; kc++) {
        if (kc < NC - 1) cp_wait1(); else cp_wait0();
        __syncthreads();
        uint32_t bb = sb + (kc & 1) * GU_STAGE;
#pragma unroll
        for (int ks = 0; ks < 4; ks++) {
            int kk = ks * 16;
            uint32_t ah[4][4], al[4][4];
            fragA(bb, wm, lane, kk, ah);
            fragA(bb + 16384, wm, lane, kk, al);
            {
                uint32_t bh[4][2], bl[4][2];
                fragB(bb + 32768, wn, lane, kk, bh);
                fragB(bb + 49152, wn, lane, kk, bl);
#pragma unroll
                for (int mt = 0; mt < 4; mt++)
#pragma unroll
                    for (int nt = 0; nt < 4; nt++) {
                        mma_bf16(accg[mt][nt], ah[mt], bh[nt]);
                        mma_bf16(accg[mt][nt], al[mt], bh[nt]);
                        mma_bf16(accg[mt][nt], ah[mt], bl[nt]);
                    }
            }
            {
                uint32_t bh[4][2], bl[4][2];
                fragB(bb + 65536, wn, lane, kk, bh);
                fragB(bb + 81920, wn, lane, kk, bl);
#pragma unroll
                for (int mt = 0; mt < 4; mt++)
#pragma unroll
                    for (int nt = 0; nt < 4; nt++) {
                        mma_bf16(accu[mt][nt], ah[mt], bh[nt]);
                        mma_bf16(accu[mt][nt], al[mt], bh[nt]);
                        mma_bf16(accu[mt][nt], ah[mt], bl[nt]);
                    }
            }
        }
        __syncthreads();
        if (kc + 2 < NC) load_stage(kc & 1, kc + 2);
    }

    // epilogue: act = silu(0.5*g) * u -> bf16 hi/lo
#pragma unroll
    for (int mt = 0; mt < 4; mt++)
#pragma unroll
        for (int nt = 0; nt < 4; nt++)
#pragma unroll
            for (int vp = 0; vp < 2; vp++) {
                int rr = wm * 64 + mt * 16 + (lane >> 2) + vp * 8;
                int cc = wn * 32 + nt * 8 + (lane & 3) * 2;
                int gr = rowt + rr;
                if (gr < ne) {
                    size_t base = (size_t)(r0 + gr) * INTER + n0 + cc;
                    __nv_bfloat16 hh[2], ll[2];
#pragma unroll
                    for (int j = 0; j < 2; j++) {
                        float gv = accg[mt][nt][vp * 2 + j] * 0.5f;
                        float sv = gv / (1.f + __expf(-gv));
                        float h = sv * accu[mt][nt][vp * 2 + j];
                        __nv_bfloat16 hi = __float2bfloat16(h);
                        hh[j] = hi;
                        ll[j] = __float2bfloat16(h - __bfloat162float(hi));
                    }
                    *reinterpret_cast<uint32_t*>(g_acth + base) = *reinterpret_cast<uint32_t*>(hh);
                    *reinterpret_cast<uint32_t*>(g_actl + base) = *reinterpret_cast<uint32_t*>(ll);
                }
            }
}

// ---------------- down GEMM ----------------
// stage layout: Ah 0, Al 16K, Bh 32K, Bl 48K (64KB/stage, 3 stages)
#define DN_STAGE 65536
#define DN_SMEM (3 * DN_STAGE)

__global__ void __launch_bounds__(256, 1)
moe_down() {
    constexpr int NC = INTER / 64;
    extern __shared__ char dsm[];
    __shared__ int sRow[128];
    uint32_t sb = smem_u32(dsm);

    int e = blockIdx.z;
    int r0 = g_offsets[e];
    int ne = g_offsets[e + 1] - r0;
    int rowt = blockIdx.y * 128;
    if (rowt >= ne) return;
    int n0 = blockIdx.x * 128;
    int tid = threadIdx.x;

    const __nv_bfloat16* Bh = g_wdh + (size_t)e * INTER * HID;
    const __nv_bfloat16* Bl = g_wdl + (size_t)e * INTER * HID;

    if (tid < 128) {
        int gr = min(rowt + tid, ne - 1);
        sRow[tid] = (r0 + gr) * INTER;
    }
    __syncthreads();

    auto load_stage = [&](int buf, int kc) {
        uint32_t bb = sb + buf * DN_STAGE;
        int k0 = kc * 64;
        load_A(bb, bb + 16384, tid, g_acth, g_actl, sRow, k0);
        load_B<HID>(bb + 32768, bb + 49152, tid, Bh, Bl, k0, n0);
        cp_commit();
    };

    load_stage(0, 0);
    load_stage(1, 1);
    load_stage(2, 2);

    int warp = tid >> 5, lane = tid & 31;
    int wm = warp >> 2, wn = warp & 3;

    float acc[4][4][4];
#pragma unroll
    for (int a = 0; a < 4; a++)
#pragma unroll
        for (int b = 0; b < 4; b++)
#pragma unroll
            for (int c = 0; c < 4; c++) acc[a][b][c] = 0.f;

    for (int kc = 0; kc < NC; kc++) {
        if (kc <= NC - 3) cp_wait2();
        else if (kc == NC - 2) cp_wait1();
        else cp_wait0();
        __syncthreads();
        uint32_t bb = sb + (kc % 3) * DN_STAGE;
#pragma unroll
        for (int ks = 0; ks < 4; ks++) {
            int kk = ks * 16;
            uint32_t ah[4][4], al[4][4];
            fragA(bb, wm, lane, kk, ah);
            fragA(bb + 16384, wm, lane, kk, al);
            uint32_t bh[4][2], bl[4][2];
            fragB(bb + 32768, wn, lane, kk, bh);
            fragB(bb + 49152, wn, lane, kk, bl);
#pragma unroll
            for (int mt = 0; mt < 4; mt++)
#pragma unroll
                for (int nt = 0; nt < 4; nt++) {
                    mma_bf16(acc[mt][nt], ah[mt], bh[nt]);
                    mma_bf16(acc[mt][nt], al[mt], bh[nt]);
                    mma_bf16(acc[mt][nt], ah[mt], bl[nt]);
                }
        }
        __syncthreads();
        if (kc + 3 < NC) load_stage(kc % 3, kc + 3);
    }

    // epilogue: 0.25 * w * acc -> g_pair_out
#pragma unroll
    for (int mt = 0; mt < 4; mt++)
#pragma unroll
        for (int nt = 0; nt < 4; nt++)
#pragma unroll
            for (int vp = 0; vp < 2; vp++) {
                int rr = wm * 64 + mt * 16 + (lane >> 2) + vp * 8;
                int cc = wn * 32 + nt * 8 + (lane & 3) * 2;
                int gr = rowt + rr;
                if (gr < ne) {
                    size_t pr = (size_t)(r0 + gr);
                    float s = 0.25f * g_row_weight[pr];
                    float2 o;
                    o.x = s * acc[mt][nt][vp * 2];
                    o.y = s * acc[mt][nt][vp * 2 + 1];
                    *reinterpret_cast<float2*>(g_pair_out + pr * HID + n0 + cc) = o;
                }
            }
}

// ---------------- combine ----------------
__global__ void combine_kernel(float* __restrict__ out, int T) {
    int i = blockIdx.x * blockDim.x + threadIdx.x;
    int total = T * (HID / 4);
    if (i >= total) return;
    int t = i / (HID / 4);
    int c4 = i % (HID / 4);
    int ra = g_row_of[t][0], rb = g_row_of[t][1];
    float4 a = reinterpret_cast<const float4*>(g_pair_out + (size_t)ra * HID)[c4];
    float4 b = reinterpret_cast<const float4*>(g_pair_out + (size_t)rb * HID)[c4];
    float4 r;
    r.x = a.x + b.x; r.y = a.y + b.y; r.z = a.z + b.z; r.w = a.w + b.w;
    reinterpret_cast<float4*>(out)[i] = r;
}

// ---------------- launch ----------------
extern "C" void kernel_launch(void* const* d_in, const int* in_sizes, int n_in,
                              void* d_out, int out_size) {
    const float* x  = (const float*)d_in[0];
    const float* wr = (const float*)d_in[1];
    const float* wg = (const float*)d_in[2];
    const float* wu = (const float*)d_in[3];
    const float* wd = (const float*)d_in[4];
    float* out = (float*)d_out;

    int T = in_sizes[0] / HID;
    int pairs = T * TKK;

    cudaFuncSetAttribute(moe_gateup, cudaFuncAttributeMaxDynamicSharedMemorySize, GU_SMEM);
    cudaFuncSetAttribute(moe_down, cudaFuncAttributeMaxDynamicSharedMemorySize, DN_SMEM);

    // routing + compaction
    router_kernel<<<(T + 7) / 8, 256>>>(x, wr, T);
    assign_kernel<<<(pairs + 255) / 256, 256>>>(pairs);
    scan_kernel<<<1, 32>>>();
    fill_kernel<<<(pairs + 255) / 256, 256>>>(pairs);

    // preconversion to bf16 hi/lo (device-side destination selection)
    convert_kernel<0><<<(T * HID / 4 + 255) / 256, 256>>>(x, T * HID / 4);
    int wsz = NE * HID * INTER / 4;
    convert_kernel<1><<<(wsz + 255) / 256, 256>>>(wg, wsz);
    convert_kernel<2><<<(wsz + 255) / 256, 256>>>(wu, wsz);
    convert_kernel<3><<<(wsz + 255) / 256, 256>>>(wd, wsz);

    int mtiles = (T + 127) / 128;
    moe_gateup<<<dim3(INTER / 128, mtiles, NE), 256, GU_SMEM>>>();
    moe_down<<<dim3(HID / 128, mtiles, NE), 256, DN_SMEM>>>();

    int tot4 = T * (HID / 4);
    combine_kernel<<<(tot4 + 255) / 256, 256>>>(out, T);
}